// round 1
// baseline (speedup 1.0000x reference)
#include <cuda_runtime.h>
#include <math.h>

#define N_NODES 100000
#define N_EDGES 20000
#define NNZV    1600000
#define D       128
#define STAR    64
#define DK      (D + STAR)   // 192

// ---------------- scratch (device globals; no allocation allowed) ----------
__device__ float g_v[132];               // v[0..127] = Wv^T a, v[128] = a.Wv_b
__device__ float g_w[N_NODES];           // exp(leaky_relu(score)) per node
__device__ float g_den[N_EDGES];         // softmax denominator per edge
__device__ int   g_cntE[N_EDGES];
__device__ int   g_offE[N_EDGES + 1];
__device__ int   g_curE[N_EDGES];
__device__ int   g_cntV[N_NODES];
__device__ int   g_offV[N_NODES + 1];
__device__ int   g_curV[N_NODES];
__device__ int   g_sV[NNZV];             // V values grouped by edge
__device__ int   g_sE[NNZV];             // E values grouped by node
__device__ float g_A[N_EDGES * D];       // per-edge aggregated X
__device__ float g_ZS[N_EDGES * DK];     // [elu(A@Wv^T+b) | S]
__device__ float g_Y[N_EDGES * D];       // transformed edge messages

// ---------------- small setup kernels --------------------------------------
__global__ void zero_kernel() {
    int i = blockIdx.x * blockDim.x + threadIdx.x;
    if (i < N_NODES) g_cntV[i] = 0;
    if (i < N_EDGES) { g_cntE[i] = 0; g_den[i] = 0.f; }
}

__global__ void compute_v_kernel(const float* __restrict__ a_w,
                                 const float* __restrict__ Wv_w,
                                 const float* __restrict__ Wv_b) {
    int j = threadIdx.x;
    float s = 0.f;
    for (int k = 0; k < D; k++) s = fmaf(a_w[k], Wv_w[k * D + j], s);
    g_v[j] = s;
    if (j == 0) {
        float c = 0.f;
        for (int k = 0; k < D; k++) c = fmaf(a_w[k], Wv_b[k], c);
        g_v[128] = c;
    }
}

// one warp per node: w[n] = exp(leaky_relu(X[n] . v + c))
__global__ void score_kernel(const float* __restrict__ X) {
    int warp = (blockIdx.x * blockDim.x + threadIdx.x) >> 5;
    int lane = threadIdx.x & 31;
    if (warp >= N_NODES) return;
    const float4* xr = reinterpret_cast<const float4*>(X + (size_t)warp * D);
    const float4* vr = reinterpret_cast<const float4*>(g_v);
    float4 x = xr[lane];
    float4 v = vr[lane];
    float s = x.x * v.x + x.y * v.y + x.z * v.z + x.w * v.w;
    #pragma unroll
    for (int o = 16; o; o >>= 1) s += __shfl_xor_sync(0xffffffffu, s, o);
    if (lane == 0) {
        s += g_v[128];
        s = (s >= 0.f) ? s : 0.2f * s;
        g_w[warp] = expf(s);
    }
}

__global__ void hist_kernel(const int* __restrict__ V, const int* __restrict__ E) {
    int i = blockIdx.x * blockDim.x + threadIdx.x;
    if (i >= NNZV) return;
    int v = V[i], e = E[i];
    atomicAdd(&g_cntE[e], 1);
    atomicAdd(&g_cntV[v], 1);
    atomicAdd(&g_den[e], g_w[v]);
}

// single-block scan (4096 elems / pass, warp-shuffle based)
__device__ __forceinline__ void scan_impl(const int* __restrict__ cnt, int n,
                                          int* __restrict__ off, int* __restrict__ cur) {
    __shared__ int warp_tot[32];
    __shared__ int carry_s;
    int tid = threadIdx.x, lane = tid & 31, wid = tid >> 5;
    if (tid == 0) carry_s = 0;
    __syncthreads();
    const int CH = 1024 * 4;
    for (int base = 0; base < n; base += CH) {
        int i0 = base + tid * 4;
        int x[4];
        #pragma unroll
        for (int k = 0; k < 4; k++) { int i = i0 + k; x[k] = (i < n) ? cnt[i] : 0; }
        int s = x[0] + x[1] + x[2] + x[3];
        int sc = s;
        #pragma unroll
        for (int o = 1; o < 32; o <<= 1) {
            int t = __shfl_up_sync(0xffffffffu, sc, o);
            if (lane >= o) sc += t;
        }
        if (lane == 31) warp_tot[wid] = sc;
        __syncthreads();
        if (wid == 0) {
            int v = warp_tot[lane];
            int vs = v;
            #pragma unroll
            for (int o = 1; o < 32; o <<= 1) {
                int t = __shfl_up_sync(0xffffffffu, vs, o);
                if (lane >= o) vs += t;
            }
            warp_tot[lane] = vs - v;  // exclusive
        }
        __syncthreads();
        int carry = carry_s;
        int ex = carry + warp_tot[wid] + (sc - s);
        #pragma unroll
        for (int k = 0; k < 4; k++) {
            int i = i0 + k;
            if (i < n) { off[i] = ex; cur[i] = ex; }
            ex += x[k];
        }
        __syncthreads();
        if (tid == 1023) carry_s = carry + warp_tot[31] + sc;
        __syncthreads();
    }
    if (tid == 0) off[n] = carry_s;
}

__global__ void scanE_kernel() { scan_impl(g_cntE, N_EDGES, g_offE, g_curE); }
__global__ void scanV_kernel() { scan_impl(g_cntV, N_NODES, g_offV, g_curV); }

__global__ void scatter_kernel(const int* __restrict__ V, const int* __restrict__ E) {
    int i = blockIdx.x * blockDim.x + threadIdx.x;
    if (i >= NNZV) return;
    int v = V[i], e = E[i];
    int pe = atomicAdd(&g_curE[e], 1);
    g_sV[pe] = v;
    int pv = atomicAdd(&g_curV[v], 1);
    g_sE[pv] = e;
}

// ---------------- tiled FP32 GEMM: C[M,N=128] = act(A[M,K] @ W[128,K]^T + b) -
// BM=64, BN=128, BK=32, 256 threads, 8x4 register tile (cols interleaved by 32)
template <int ACT>
__global__ void gemm_kernel(const float* __restrict__ A, int lda,
                            const float* __restrict__ W,
                            const float* __restrict__ bias,
                            float* __restrict__ C, int ldc,
                            int M, int K) {
    __shared__ float As[64][33];
    __shared__ float Ws[32][129];
    int tid = threadIdx.x;
    int warp = tid >> 5, lane = tid & 31;
    int rowTile = blockIdx.x * 64;
    int row0 = warp * 8;
    float acc[8][4] = {};
    for (int k0 = 0; k0 < K; k0 += 32) {
        #pragma unroll
        for (int i = 0; i < 8; i++) {
            int r = tid >> 2;
            int c = ((tid & 3) << 3) + i;
            int gr = rowTile + r;
            As[r][c] = (gr < M) ? A[(size_t)gr * lda + k0 + c] : 0.f;
        }
        #pragma unroll
        for (int i = 0; i < 16; i++) {
            int col = tid >> 1;
            int kk = ((tid & 1) << 4) + i;
            Ws[kk][col] = W[col * K + k0 + kk];
        }
        __syncthreads();
        #pragma unroll
        for (int kk = 0; kk < 32; kk++) {
            float a[8], w[4];
            #pragma unroll
            for (int i = 0; i < 8; i++) a[i] = As[row0 + i][kk];
            #pragma unroll
            for (int j = 0; j < 4; j++) w[j] = Ws[kk][lane + 32 * j];
            #pragma unroll
            for (int i = 0; i < 8; i++)
                #pragma unroll
                for (int j = 0; j < 4; j++) acc[i][j] = fmaf(a[i], w[j], acc[i][j]);
        }
        __syncthreads();
    }
    #pragma unroll
    for (int i = 0; i < 8; i++) {
        int gr = rowTile + row0 + i;
        if (gr >= M) continue;
        #pragma unroll
        for (int j = 0; j < 4; j++) {
            float val = acc[i][j] + bias[lane + 32 * j];
            if (ACT == 1) val = (val > 0.f) ? val : expm1f(val);
            C[(size_t)gr * ldc + lane + 32 * j] = val;
        }
    }
}

// ---------------- segment aggregations --------------------------------------
// one block per edge: A[e] = sum_i soft_i * X[v_i]
__global__ void aggE_kernel(const float* __restrict__ X) {
    int e = blockIdx.x, d = threadIdx.x;
    int beg = g_offE[e], end = g_offE[e + 1];
    float den = g_den[e];
    float inv = (end > beg && den != 0.f) ? 1.f / den : 0.f;
    __shared__ int sh_i[128];
    __shared__ float sh_c[128];
    float acc = 0.f;
    for (int base = beg; base < end; base += 128) {
        int nn = min(128, end - base);
        __syncthreads();
        if (d < nn) {
            int v = g_sV[base + d];
            sh_i[d] = v;
            sh_c[d] = g_w[v] * inv;
        }
        __syncthreads();
        int j = 0;
        for (; j + 4 <= nn; j += 4) {
            int v0 = sh_i[j], v1 = sh_i[j + 1], v2 = sh_i[j + 2], v3 = sh_i[j + 3];
            float c0 = sh_c[j], c1 = sh_c[j + 1], c2 = sh_c[j + 2], c3 = sh_c[j + 3];
            float x0 = X[(size_t)v0 * D + d];
            float x1 = X[(size_t)v1 * D + d];
            float x2 = X[(size_t)v2 * D + d];
            float x3 = X[(size_t)v3 * D + d];
            acc = fmaf(c0, x0, acc);
            acc = fmaf(c1, x1, acc);
            acc = fmaf(c2, x2, acc);
            acc = fmaf(c3, x3, acc);
        }
        for (; j < nn; j++) acc = fmaf(sh_c[j], X[(size_t)sh_i[j] * D + d], acc);
    }
    g_A[(size_t)e * D + d] = acc;
}

__global__ void copyS_kernel(const float* __restrict__ S) {
    int i = blockIdx.x * blockDim.x + threadIdx.x;
    if (i >= N_EDGES * STAR) return;
    int e = i / STAR, j = i % STAR;
    g_ZS[(size_t)e * DK + D + j] = S[i];
}

// one block per node: out[n] = X_init[n] + elu(mean_i Y[e_i])
__global__ void aggV_kernel(float* __restrict__ out) {
    int n = blockIdx.x, d = threadIdx.x;
    int beg = g_offV[n], end = g_offV[n + 1];
    __shared__ int sh_e[128];
    float acc = 0.f;
    for (int base = beg; base < end; base += 128) {
        int nn = min(128, end - base);
        __syncthreads();
        if (d < nn) sh_e[d] = g_sE[base + d];
        __syncthreads();
        int j = 0;
        for (; j + 4 <= nn; j += 4) {
            float y0 = g_Y[(size_t)sh_e[j] * D + d];
            float y1 = g_Y[(size_t)sh_e[j + 1] * D + d];
            float y2 = g_Y[(size_t)sh_e[j + 2] * D + d];
            float y3 = g_Y[(size_t)sh_e[j + 3] * D + d];
            acc += y0 + y1 + y2 + y3;
        }
        for (; j < nn; j++) acc += g_Y[(size_t)sh_e[j] * D + d];
    }
    int cnt = end - beg;
    float xm = acc / (float)(cnt > 0 ? cnt : 1);
    xm = (xm > 0.f) ? xm : expm1f(xm);
    size_t idx = (size_t)n * D + d;
    out[idx] = out[idx] + xm;
}

// ---------------- launch -----------------------------------------------------
extern "C" void kernel_launch(void* const* d_in, const int* in_sizes, int n_in,
                              void* d_out, int out_size) {
    const float* X    = (const float*)d_in[0];
    const int*   V    = (const int*)d_in[1];
    const int*   E    = (const int*)d_in[2];
    const float* S    = (const float*)d_in[3];
    const float* Wx_w = (const float*)d_in[4];
    const float* Wx_b = (const float*)d_in[5];
    const float* Wv_w = (const float*)d_in[6];
    const float* Wv_b = (const float*)d_in[7];
    const float* a_w  = (const float*)d_in[8];
    const float* Wt_w = (const float*)d_in[9];
    const float* Wt_b = (const float*)d_in[10];
    float* out = (float*)d_out;

    float *pA = nullptr, *pZS = nullptr, *pY = nullptr;
    cudaGetSymbolAddress((void**)&pA,  g_A);
    cudaGetSymbolAddress((void**)&pZS, g_ZS);
    cudaGetSymbolAddress((void**)&pY,  g_Y);

    zero_kernel<<<(N_NODES + 255) / 256, 256>>>();
    compute_v_kernel<<<1, 128>>>(a_w, Wv_w, Wv_b);
    score_kernel<<<(N_NODES * 32 + 127) / 128, 128>>>(X);
    hist_kernel<<<(NNZV + 255) / 256, 256>>>(V, E);
    scanE_kernel<<<1, 1024>>>();
    scanV_kernel<<<1, 1024>>>();
    scatter_kernel<<<(NNZV + 255) / 256, 256>>>(V, E);

    // X_init straight into the output buffer
    gemm_kernel<0><<<(N_NODES + 63) / 64, 256>>>(X, D, Wx_w, Wx_b, out, D, N_NODES, D);

    aggE_kernel<<<N_EDGES, 128>>>(X);

    // Z = elu(A @ Wv^T + Wv_b) into the first 128 cols of g_ZS (ldc = 192)
    gemm_kernel<1><<<(N_EDGES + 63) / 64, 256>>>(pA, D, Wv_w, Wv_b, pZS, DK, N_EDGES, D);
    copyS_kernel<<<(N_EDGES * STAR + 255) / 256, 256>>>(S);

    // Y = [Z | S] @ Wt^T + Wt_b
    gemm_kernel<0><<<(N_EDGES + 63) / 64, 256>>>(pZS, DK, Wt_w, Wt_b, pY, D, N_EDGES, DK);

    aggV_kernel<<<N_NODES, 128>>>(out);
}

// round 3
// speedup vs baseline: 1.5170x; 1.5170x over previous
#include <cuda_runtime.h>
#include <math.h>

#define N_NODES 100000
#define N_EDGES 20000
#define NNZV    1600000
#define D       128
#define STAR    64
#define DK      (D + STAR)   // 192
#define NBV     98           // ceil(100000/1024)
#define NBE     20           // ceil(20000/1024)

// ---------------- scratch (device globals; no allocation allowed) ----------
__device__ __align__(16) float g_v[132];     // v[0..127] = Wv^T a, v[128] = a.Wv_b
__device__ float g_w[N_NODES];               // exp(leaky_relu(score)) per node
__device__ int   g_cntE[N_EDGES];
__device__ int   g_offE[N_EDGES + 1];
__device__ int   g_curE[N_EDGES];
__device__ int   g_cntV[N_NODES];
__device__ int   g_offV[N_NODES + 1];
__device__ int   g_curV[N_NODES];
__device__ int   g_bsV[NBV + 1];
__device__ int   g_bsE[NBE + 1];
__device__ int   g_sV[NNZV];                 // V values grouped by edge
__device__ int   g_sE[NNZV];                 // E values grouped by node
__device__ __align__(16) float g_A[N_EDGES * D];    // per-edge aggregated X
__device__ __align__(16) float g_ZS[N_EDGES * DK];  // [elu(A@Wv^T+b) | S]
__device__ __align__(16) float g_Y[N_EDGES * D];    // transformed edge messages

// ---------------- small setup kernels --------------------------------------
__global__ void zero_kernel() {
    int i = blockIdx.x * blockDim.x + threadIdx.x;
    if (i < N_NODES) g_cntV[i] = 0;
    if (i < N_EDGES) g_cntE[i] = 0;
}

__global__ void compute_v_kernel(const float* __restrict__ a_w,
                                 const float* __restrict__ Wv_w,
                                 const float* __restrict__ Wv_b) {
    int j = threadIdx.x;
    float s = 0.f;
    for (int k = 0; k < D; k++) s = fmaf(a_w[k], Wv_w[k * D + j], s);
    g_v[j] = s;
    if (j == 0) {
        float c = 0.f;
        for (int k = 0; k < D; k++) c = fmaf(a_w[k], Wv_b[k], c);
        g_v[128] = c;
    }
}

// one warp per node: w[n] = exp(leaky_relu(X[n] . v + c))
__global__ void score_kernel(const float* __restrict__ X) {
    int warp = (blockIdx.x * blockDim.x + threadIdx.x) >> 5;
    int lane = threadIdx.x & 31;
    if (warp >= N_NODES) return;
    const float4* xr = reinterpret_cast<const float4*>(X + (size_t)warp * D);
    const float4* vr = reinterpret_cast<const float4*>(g_v);
    float4 x = xr[lane];
    float4 v = vr[lane];
    float s = x.x * v.x + x.y * v.y + x.z * v.z + x.w * v.w;
    #pragma unroll
    for (int o = 16; o; o >>= 1) s += __shfl_xor_sync(0xffffffffu, s, o);
    if (lane == 0) {
        s += g_v[128];
        s = (s >= 0.f) ? s : 0.2f * s;
        g_w[warp] = expf(s);
    }
}

__global__ void hist_kernel(const int* __restrict__ V, const int* __restrict__ E) {
    int i = blockIdx.x * blockDim.x + threadIdx.x;
    if (i >= NNZV) return;
    atomicAdd(&g_cntE[E[i]], 1);
    atomicAdd(&g_cntV[V[i]], 1);
}

// ---------------- multi-block exclusive scan --------------------------------
// pass1: per-block exclusive scan, block totals into bsum
__global__ void scan1_kernel(const int* __restrict__ cnt, int n,
                             int* __restrict__ off, int* __restrict__ bsum) {
    __shared__ int wt[32];
    int tid = threadIdx.x, lane = tid & 31, wid = tid >> 5;
    int i = blockIdx.x * 1024 + tid;
    int x = (i < n) ? cnt[i] : 0;
    int s = x;
    #pragma unroll
    for (int o = 1; o < 32; o <<= 1) {
        int t = __shfl_up_sync(0xffffffffu, s, o);
        if (lane >= o) s += t;
    }
    if (lane == 31) wt[wid] = s;
    __syncthreads();
    if (wid == 0) {
        int v = wt[lane];
        int vs = v;
        #pragma unroll
        for (int o = 1; o < 32; o <<= 1) {
            int t = __shfl_up_sync(0xffffffffu, vs, o);
            if (lane >= o) vs += t;
        }
        wt[lane] = vs - v;
    }
    __syncthreads();
    int ex = wt[wid] + s - x;
    if (i < n) off[i] = ex;
    if (tid == 1023) bsum[blockIdx.x] = ex + x;
}

// pass2: scan the (tiny) block-sum arrays
__global__ void scan2_kernel() {
    if (threadIdx.x == 0) {
        int a = 0;
        for (int i = 0; i < NBV; i++) { int t = g_bsV[i]; g_bsV[i] = a; a += t; }
        g_bsV[NBV] = a;
    }
    if (threadIdx.x == 32) {
        int a = 0;
        for (int i = 0; i < NBE; i++) { int t = g_bsE[i]; g_bsE[i] = a; a += t; }
        g_bsE[NBE] = a;
    }
}

// pass3: add block offsets, fill cur + final sentinel
__global__ void scan3_kernel(int* __restrict__ off, int* __restrict__ cur,
                             const int* __restrict__ bsum, int n, int nb) {
    int i = blockIdx.x * blockDim.x + threadIdx.x;
    if (i < n) {
        int v = off[i] + bsum[i >> 10];
        off[i] = v;
        cur[i] = v;
    } else if (i == n) {
        off[n] = bsum[nb];
    }
}

__global__ void scatter_kernel(const int* __restrict__ V, const int* __restrict__ E) {
    int i = blockIdx.x * blockDim.x + threadIdx.x;
    if (i >= NNZV) return;
    int v = V[i], e = E[i];
    int pe = atomicAdd(&g_curE[e], 1);
    g_sV[pe] = v;
    int pv = atomicAdd(&g_curV[v], 1);
    g_sE[pv] = e;
}

// ---------------- TF32 tensor-core GEMM -------------------------------------
// C[M, 128] = act(A[M,K] @ W[128,K]^T + b).  BM=128, BN=128, BK=16.
// 256 threads = 8 warps (2 x 4); warp tile 64x32 via m16n8k8 tf32 mma.
__device__ __forceinline__ unsigned f2tf(float f) {
    unsigned r;
    asm("cvt.rna.tf32.f32 %0, %1;" : "=r"(r) : "f"(f));
    return r;
}

__device__ __forceinline__ void mma_tf32(float c[4], const unsigned a[4],
                                         const unsigned b[2]) {
    asm volatile(
        "mma.sync.aligned.m16n8k8.row.col.f32.tf32.tf32.f32 "
        "{%0,%1,%2,%3}, {%4,%5,%6,%7}, {%8,%9}, {%0,%1,%2,%3};"
        : "+f"(c[0]), "+f"(c[1]), "+f"(c[2]), "+f"(c[3])
        : "r"(a[0]), "r"(a[1]), "r"(a[2]), "r"(a[3]), "r"(b[0]), "r"(b[1]));
}

#define AS_STRIDE 20
#define BS_STRIDE 136

template <int ACT>
__global__ void gemm_tc_kernel(const float* __restrict__ A, int lda,
                               const float* __restrict__ W,
                               const float* __restrict__ bias,
                               float* __restrict__ C, int ldc,
                               int M, int K) {
    __shared__ unsigned As[128 * AS_STRIDE];
    __shared__ unsigned Bs[16 * BS_STRIDE];
    const int tid = threadIdx.x, lane = tid & 31, warp = tid >> 5;
    const int wr = warp >> 2, wc = warp & 3;
    const int g = lane >> 2, tg = lane & 3;
    const int rowTile = blockIdx.x * 128;

    float acc[4][4][4];
    #pragma unroll
    for (int mt = 0; mt < 4; mt++)
        #pragma unroll
        for (int nt = 0; nt < 4; nt++)
            #pragma unroll
            for (int q = 0; q < 4; q++) acc[mt][nt][q] = 0.f;

    for (int k0 = 0; k0 < K; k0 += 16) {
        // stage A: 128 rows x 16 cols, 8 floats/thread
        {
            int r = tid >> 1, c = (tid & 1) * 8;
            int gr = rowTile + r;
            float4 v0 = make_float4(0.f, 0.f, 0.f, 0.f), v1 = v0;
            if (gr < M) {
                const float* p = A + (size_t)gr * lda + k0 + c;
                v0 = *reinterpret_cast<const float4*>(p);
                v1 = *reinterpret_cast<const float4*>(p + 4);
            }
            unsigned* dst = &As[r * AS_STRIDE + c];
            dst[0] = f2tf(v0.x); dst[1] = f2tf(v0.y);
            dst[2] = f2tf(v0.z); dst[3] = f2tf(v0.w);
            dst[4] = f2tf(v1.x); dst[5] = f2tf(v1.y);
            dst[6] = f2tf(v1.z); dst[7] = f2tf(v1.w);
        }
        // stage B (transposed): Bs[k][n] from W[n][k]
        {
            int n = tid >> 1, c = (tid & 1) * 8;
            const float* p = W + (size_t)n * K + k0 + c;
            float4 v0 = *reinterpret_cast<const float4*>(p);
            float4 v1 = *reinterpret_cast<const float4*>(p + 4);
            Bs[(c + 0) * BS_STRIDE + n] = f2tf(v0.x);
            Bs[(c + 1) * BS_STRIDE + n] = f2tf(v0.y);
            Bs[(c + 2) * BS_STRIDE + n] = f2tf(v0.z);
            Bs[(c + 3) * BS_STRIDE + n] = f2tf(v0.w);
            Bs[(c + 4) * BS_STRIDE + n] = f2tf(v1.x);
            Bs[(c + 5) * BS_STRIDE + n] = f2tf(v1.y);
            Bs[(c + 6) * BS_STRIDE + n] = f2tf(v1.z);
            Bs[(c + 7) * BS_STRIDE + n] = f2tf(v1.w);
        }
        __syncthreads();
        #pragma unroll
        for (int ks = 0; ks < 16; ks += 8) {
            unsigned af[4][4], bf[4][2];
            #pragma unroll
            for (int mt = 0; mt < 4; mt++) {
                int r0 = (wr * 64 + mt * 16 + g) * AS_STRIDE;
                af[mt][0] = As[r0 + ks + tg];
                af[mt][1] = As[r0 + 8 * AS_STRIDE + ks + tg];
                af[mt][2] = As[r0 + ks + tg + 4];
                af[mt][3] = As[r0 + 8 * AS_STRIDE + ks + tg + 4];
            }
            #pragma unroll
            for (int nt = 0; nt < 4; nt++) {
                int n0 = wc * 32 + nt * 8 + g;
                bf[nt][0] = Bs[(ks + tg) * BS_STRIDE + n0];
                bf[nt][1] = Bs[(ks + tg + 4) * BS_STRIDE + n0];
            }
            #pragma unroll
            for (int mt = 0; mt < 4; mt++)
                #pragma unroll
                for (int nt = 0; nt < 4; nt++) mma_tf32(acc[mt][nt], af[mt], bf[nt]);
        }
        __syncthreads();
    }
    // epilogue
    #pragma unroll
    for (int mt = 0; mt < 4; mt++) {
        int gr0 = rowTile + wr * 64 + mt * 16 + g;
        int gr1 = gr0 + 8;
        #pragma unroll
        for (int nt = 0; nt < 4; nt++) {
            int col = wc * 32 + nt * 8 + tg * 2;
            float b0 = __ldg(&bias[col]), b1 = __ldg(&bias[col + 1]);
            float v0 = acc[mt][nt][0] + b0, v1 = acc[mt][nt][1] + b1;
            float v2 = acc[mt][nt][2] + b0, v3 = acc[mt][nt][3] + b1;
            if (ACT == 1) {
                v0 = (v0 > 0.f) ? v0 : expm1f(v0);
                v1 = (v1 > 0.f) ? v1 : expm1f(v1);
                v2 = (v2 > 0.f) ? v2 : expm1f(v2);
                v3 = (v3 > 0.f) ? v3 : expm1f(v3);
            }
            if (gr0 < M) {
                float2 p = make_float2(v0, v1);
                *reinterpret_cast<float2*>(&C[(size_t)gr0 * ldc + col]) = p;
            }
            if (gr1 < M) {
                float2 p = make_float2(v2, v3);
                *reinterpret_cast<float2*>(&C[(size_t)gr1 * ldc + col]) = p;
            }
        }
    }
}

// ---------------- segment aggregations --------------------------------------
// one block per edge: A[e] = (sum_i w_i X[v_i]) / (sum_i w_i)
__global__ void aggE_kernel(const float* __restrict__ X) {
    int e = blockIdx.x, d = threadIdx.x;
    int beg = g_offE[e], end = g_offE[e + 1];
    __shared__ int sh_i[128];
    __shared__ float sh_c[128];
    float acc = 0.f, wsum = 0.f;
    for (int base = beg; base < end; base += 128) {
        int nn = min(128, end - base);
        __syncthreads();
        if (d < nn) {
            int v = g_sV[base + d];
            sh_i[d] = v;
            sh_c[d] = g_w[v];
        }
        __syncthreads();
        int j = 0;
        for (; j + 4 <= nn; j += 4) {
            int v0 = sh_i[j], v1 = sh_i[j + 1], v2 = sh_i[j + 2], v3 = sh_i[j + 3];
            float c0 = sh_c[j], c1 = sh_c[j + 1], c2 = sh_c[j + 2], c3 = sh_c[j + 3];
            float x0 = X[(size_t)v0 * D + d];
            float x1 = X[(size_t)v1 * D + d];
            float x2 = X[(size_t)v2 * D + d];
            float x3 = X[(size_t)v3 * D + d];
            acc = fmaf(c0, x0, acc);
            acc = fmaf(c1, x1, acc);
            acc = fmaf(c2, x2, acc);
            acc = fmaf(c3, x3, acc);
            wsum += (c0 + c1) + (c2 + c3);
        }
        for (; j < nn; j++) {
            float c = sh_c[j];
            acc = fmaf(c, X[(size_t)sh_i[j] * D + d], acc);
            wsum += c;
        }
    }
    float inv = (wsum > 0.f) ? 1.f / wsum : 0.f;
    g_A[(size_t)e * D + d] = acc * inv;
}

__global__ void copyS_kernel(const float* __restrict__ S) {
    int i = blockIdx.x * blockDim.x + threadIdx.x;
    if (i >= N_EDGES * STAR) return;
    int e = i / STAR, j = i % STAR;
    g_ZS[(size_t)e * DK + D + j] = S[i];
}

// one block per node: out[n] += elu(mean_i Y[e_i])
__global__ void aggV_kernel(float* __restrict__ out) {
    int n = blockIdx.x, d = threadIdx.x;
    int beg = g_offV[n], end = g_offV[n + 1];
    __shared__ int sh_e[128];
    float acc = 0.f;
    for (int base = beg; base < end; base += 128) {
        int nn = min(128, end - base);
        __syncthreads();
        if (d < nn) sh_e[d] = g_sE[base + d];
        __syncthreads();
        int j = 0;
        for (; j + 4 <= nn; j += 4) {
            float y0 = g_Y[(size_t)sh_e[j] * D + d];
            float y1 = g_Y[(size_t)sh_e[j + 1] * D + d];
            float y2 = g_Y[(size_t)sh_e[j + 2] * D + d];
            float y3 = g_Y[(size_t)sh_e[j + 3] * D + d];
            acc += (y0 + y1) + (y2 + y3);
        }
        for (; j < nn; j++) acc += g_Y[(size_t)sh_e[j] * D + d];
    }
    int cnt = end - beg;
    float xm = acc / (float)(cnt > 0 ? cnt : 1);
    xm = (xm > 0.f) ? xm : expm1f(xm);
    size_t idx = (size_t)n * D + d;
    out[idx] = out[idx] + xm;
}

// ---------------- launch -----------------------------------------------------
extern "C" void kernel_launch(void* const* d_in, const int* in_sizes, int n_in,
                              void* d_out, int out_size) {
    const float* X    = (const float*)d_in[0];
    const int*   V    = (const int*)d_in[1];
    const int*   E    = (const int*)d_in[2];
    const float* S    = (const float*)d_in[3];
    const float* Wx_w = (const float*)d_in[4];
    const float* Wx_b = (const float*)d_in[5];
    const float* Wv_w = (const float*)d_in[6];
    const float* Wv_b = (const float*)d_in[7];
    const float* a_w  = (const float*)d_in[8];
    const float* Wt_w = (const float*)d_in[9];
    const float* Wt_b = (const float*)d_in[10];
    float* out = (float*)d_out;

    float *pA = nullptr, *pZS = nullptr, *pY = nullptr;
    int *pCntE = nullptr, *pCntV = nullptr, *pOffE = nullptr, *pOffV = nullptr;
    int *pCurE = nullptr, *pCurV = nullptr, *pBsE = nullptr, *pBsV = nullptr;
    cudaGetSymbolAddress((void**)&pA,  g_A);
    cudaGetSymbolAddress((void**)&pZS, g_ZS);
    cudaGetSymbolAddress((void**)&pY,  g_Y);
    cudaGetSymbolAddress((void**)&pCntE, g_cntE);
    cudaGetSymbolAddress((void**)&pCntV, g_cntV);
    cudaGetSymbolAddress((void**)&pOffE, g_offE);
    cudaGetSymbolAddress((void**)&pOffV, g_offV);
    cudaGetSymbolAddress((void**)&pCurE, g_curE);
    cudaGetSymbolAddress((void**)&pCurV, g_curV);
    cudaGetSymbolAddress((void**)&pBsE, g_bsE);
    cudaGetSymbolAddress((void**)&pBsV, g_bsV);

    zero_kernel<<<(N_NODES + 255) / 256, 256>>>();
    compute_v_kernel<<<1, 128>>>(a_w, Wv_w, Wv_b);
    score_kernel<<<(N_NODES * 32 + 127) / 128, 128>>>(X);
    hist_kernel<<<(NNZV + 255) / 256, 256>>>(V, E);

    scan1_kernel<<<NBV, 1024>>>(pCntV, N_NODES, pOffV, pBsV);
    scan1_kernel<<<NBE, 1024>>>(pCntE, N_EDGES, pOffE, pBsE);
    scan2_kernel<<<1, 64>>>();
    scan3_kernel<<<(N_NODES + 256) / 256, 256>>>(pOffV, pCurV, pBsV, N_NODES, NBV);
    scan3_kernel<<<(N_EDGES + 256) / 256, 256>>>(pOffE, pCurE, pBsE, N_EDGES, NBE);

    scatter_kernel<<<(NNZV + 255) / 256, 256>>>(V, E);

    // X_init straight into the output buffer
    gemm_tc_kernel<0><<<(N_NODES + 127) / 128, 256>>>(X, D, Wx_w, Wx_b, out, D,
                                                      N_NODES, D);

    aggE_kernel<<<N_EDGES, 128>>>(X);

    // Z = elu(A @ Wv^T + Wv_b) into first 128 cols of g_ZS (ldc = 192)
    gemm_tc_kernel<1><<<(N_EDGES + 127) / 128, 256>>>(pA, D, Wv_w, Wv_b, pZS, DK,
                                                      N_EDGES, D);
    copyS_kernel<<<(N_EDGES * STAR + 255) / 256, 256>>>(S);

    // Y = [Z | S] @ Wt^T + Wt_b
    gemm_tc_kernel<0><<<(N_EDGES + 127) / 128, 256>>>(pZS, DK, Wt_w, Wt_b, pY, D,
                                                      N_EDGES, DK);

    aggV_kernel<<<N_NODES, 128>>>(out);
}

// round 4
// speedup vs baseline: 2.0514x; 1.3523x over previous
#include <cuda_runtime.h>
#include <cuda_bf16.h>
#include <math.h>

#define N_NODES 100000
#define N_EDGES 20000
#define NNZV    1600000
#define D       128
#define STAR    64
#define DK      (D + STAR)   // 192
#define NBV     98           // ceil(100000/1024)
#define NBE     20           // ceil(20000/1024)

// ---------------- scratch (device globals; no allocation allowed) ----------
__device__ __align__(16) float g_v[132];     // v[0..127] = Wv^T a, v[128] = a.Wv_b
__device__ float g_w[N_NODES];               // exp(leaky_relu(score)) per node
__device__ int   g_cntE[N_EDGES];
__device__ int   g_offE[N_EDGES + 1];
__device__ int   g_curE[N_EDGES];
__device__ int   g_cntV[N_NODES];
__device__ int   g_offV[N_NODES + 1];
__device__ int   g_curV[N_NODES];
__device__ int   g_bsV[NBV + 1];
__device__ int   g_bsE[NBE + 1];
__device__ int   g_sV[NNZV];                 // V values grouped by edge
__device__ int   g_sE[NNZV];                 // E values grouped by node
__device__ __align__(16) float g_A[N_EDGES * D];    // per-edge aggregated X (fp32)
__device__ __align__(16) float g_ZS[N_EDGES * DK];  // [elu(A@Wv^T+b) | S]
__device__ __align__(16) __nv_bfloat162 g_Xb[N_NODES * 64];  // X in bf16
__device__ __align__(16) __nv_bfloat162 g_Yb[N_EDGES * 64];  // Y in bf16

// ---------------- setup: zero counters + compute v -------------------------
__global__ void setup_kernel(const float* __restrict__ a_w,
                             const float* __restrict__ Wv_w,
                             const float* __restrict__ Wv_b) {
    int b = blockIdx.x;
    if (b < 391) {
        int i = b * 256 + threadIdx.x;
        if (i < N_NODES) g_cntV[i] = 0;
        if (i < N_EDGES) g_cntE[i] = 0;
    } else {
        int j = threadIdx.x;
        if (j < 128) {
            float s = 0.f;
            for (int k = 0; k < D; k++) s = fmaf(a_w[k], Wv_w[k * D + j], s);
            g_v[j] = s;
            if (j == 0) {
                float c = 0.f;
                for (int k = 0; k < D; k++) c = fmaf(a_w[k], Wv_b[k], c);
                g_v[128] = c;
            }
        }
    }
}

// ---------------- mega1: hist + score/convert + copyS (independent) --------
#define HIST_BLOCKS  3125    // 2 incidences / thread
#define SCORE_BLOCKS 12500   // 8 nodes / block (warp per node)
#define COPYS_BLOCKS 1250    // float4 per thread

__global__ void __launch_bounds__(256) mega1_kernel(
        const int* __restrict__ V, const int* __restrict__ E,
        const float* __restrict__ X, const float* __restrict__ S) {
    int b = blockIdx.x;
    int tid = threadIdx.x;
    if (b < HIST_BLOCKS) {
        int i = b * 256 + tid;
        int2 v = reinterpret_cast<const int2*>(V)[i];
        int2 e = reinterpret_cast<const int2*>(E)[i];
        atomicAdd(&g_cntE[e.x], 1);
        atomicAdd(&g_cntE[e.y], 1);
        atomicAdd(&g_cntV[v.x], 1);
        atomicAdd(&g_cntV[v.y], 1);
    } else if (b < HIST_BLOCKS + SCORE_BLOCKS) {
        int node = (b - HIST_BLOCKS) * 8 + (tid >> 5);
        int lane = tid & 31;
        const float4* xr = reinterpret_cast<const float4*>(X + (size_t)node * D);
        const float4* vr = reinterpret_cast<const float4*>(g_v);
        float4 x = xr[lane];
        float4 v = vr[lane];
        // bf16 copy of X (free: we already read the row)
        __nv_bfloat162 p0 = __float22bfloat162_rn(make_float2(x.x, x.y));
        __nv_bfloat162 p1 = __float22bfloat162_rn(make_float2(x.z, x.w));
        uint2 packed;
        packed.x = *reinterpret_cast<unsigned*>(&p0);
        packed.y = *reinterpret_cast<unsigned*>(&p1);
        *reinterpret_cast<uint2*>(&g_Xb[(size_t)node * 64 + lane * 2]) = packed;
        float s = x.x * v.x + x.y * v.y + x.z * v.z + x.w * v.w;
        #pragma unroll
        for (int o = 16; o; o >>= 1) s += __shfl_xor_sync(0xffffffffu, s, o);
        if (lane == 0) {
            s += g_v[128];
            s = (s >= 0.f) ? s : 0.2f * s;
            g_w[node] = expf(s);
        }
    } else {
        // copy S into g_ZS cols [128,192): 4 floats / thread
        int idx4 = (b - HIST_BLOCKS - SCORE_BLOCKS) * 256 + tid;  // < 1.28M/4
        int e = idx4 >> 4;          // 16 float4 per edge row
        int j4 = (idx4 & 15) << 2;
        float4 val = *reinterpret_cast<const float4*>(&S[(size_t)e * STAR + j4]);
        *reinterpret_cast<float4*>(&g_ZS[(size_t)e * DK + D + j4]) = val;
    }
}

// ---------------- multi-block exclusive scan --------------------------------
__device__ __forceinline__ void scan1_body(const int* __restrict__ cnt, int n,
                                           int* __restrict__ off,
                                           int* __restrict__ bsum, int blk) {
    __shared__ int wt[32];
    int tid = threadIdx.x, lane = tid & 31, wid = tid >> 5;
    int i = blk * 1024 + tid;
    int x = (i < n) ? cnt[i] : 0;
    int s = x;
    #pragma unroll
    for (int o = 1; o < 32; o <<= 1) {
        int t = __shfl_up_sync(0xffffffffu, s, o);
        if (lane >= o) s += t;
    }
    if (lane == 31) wt[wid] = s;
    __syncthreads();
    if (wid == 0) {
        int v = wt[lane];
        int vs = v;
        #pragma unroll
        for (int o = 1; o < 32; o <<= 1) {
            int t = __shfl_up_sync(0xffffffffu, vs, o);
            if (lane >= o) vs += t;
        }
        wt[lane] = vs - v;
    }
    __syncthreads();
    int ex = wt[wid] + s - x;
    if (i < n) off[i] = ex;
    if (tid == 1023) bsum[blk] = ex + x;
}

__global__ void scan1_kernel() {
    int b = blockIdx.x;
    if (b < NBV) scan1_body(g_cntV, N_NODES, g_offV, g_bsV, b);
    else scan1_body(g_cntE, N_EDGES, g_offE, g_bsE, b - NBV);
}

__global__ void scan2_kernel() {
    if (threadIdx.x == 0) {
        int a = 0;
        for (int i = 0; i < NBV; i++) { int t = g_bsV[i]; g_bsV[i] = a; a += t; }
        g_bsV[NBV] = a;
    }
    if (threadIdx.x == 32) {
        int a = 0;
        for (int i = 0; i < NBE; i++) { int t = g_bsE[i]; g_bsE[i] = a; a += t; }
        g_bsE[NBE] = a;
    }
}

#define S3V 391   // ceil(100001/256)
#define S3E 79    // ceil(20001/256)
__global__ void scan3_kernel() {
    int b = blockIdx.x;
    if (b < S3V) {
        int i = b * 256 + threadIdx.x;
        if (i < N_NODES) {
            int v = g_offV[i] + g_bsV[i >> 10];
            g_offV[i] = v;
            g_curV[i] = v;
        } else if (i == N_NODES) g_offV[N_NODES] = g_bsV[NBV];
    } else {
        int i = (b - S3V) * 256 + threadIdx.x;
        if (i < N_EDGES) {
            int v = g_offE[i] + g_bsE[i >> 10];
            g_offE[i] = v;
            g_curE[i] = v;
        } else if (i == N_EDGES) g_offE[N_EDGES] = g_bsE[NBE];
    }
}

__global__ void scatter_kernel(const int* __restrict__ V, const int* __restrict__ E) {
    int i = blockIdx.x * blockDim.x + threadIdx.x;
    if (i >= NNZV / 2) return;
    int2 v = reinterpret_cast<const int2*>(V)[i];
    int2 e = reinterpret_cast<const int2*>(E)[i];
    int pe0 = atomicAdd(&g_curE[e.x], 1);
    g_sV[pe0] = v.x;
    int pe1 = atomicAdd(&g_curE[e.y], 1);
    g_sV[pe1] = v.y;
    int pv0 = atomicAdd(&g_curV[v.x], 1);
    g_sE[pv0] = e.x;
    int pv1 = atomicAdd(&g_curV[v.y], 1);
    g_sE[pv1] = e.y;
}

// ---------------- TF32 tensor-core GEMM -------------------------------------
__device__ __forceinline__ unsigned f2tf(float f) {
    unsigned r;
    asm("cvt.rna.tf32.f32 %0, %1;" : "=r"(r) : "f"(f));
    return r;
}

__device__ __forceinline__ void mma_tf32(float c[4], const unsigned a[4],
                                         const unsigned b[2]) {
    asm volatile(
        "mma.sync.aligned.m16n8k8.row.col.f32.tf32.tf32.f32 "
        "{%0,%1,%2,%3}, {%4,%5,%6,%7}, {%8,%9}, {%0,%1,%2,%3};"
        : "+f"(c[0]), "+f"(c[1]), "+f"(c[2]), "+f"(c[3])
        : "r"(a[0]), "r"(a[1]), "r"(a[2]), "r"(a[3]), "r"(b[0]), "r"(b[1]));
}

#define AS_STRIDE 20
#define BS_STRIDE 136

// ACT: 0 none, 1 elu. BF16OUT: write bf16 (ldc in bf16 elems)
template <int ACT, int BF16OUT>
__global__ void gemm_tc_kernel(const float* __restrict__ A, int lda,
                               const float* __restrict__ W,
                               const float* __restrict__ bias,
                               void* __restrict__ Cv, int ldc,
                               int M, int K) {
    __shared__ unsigned As[128 * AS_STRIDE];
    __shared__ unsigned Bs[16 * BS_STRIDE];
    const int tid = threadIdx.x, lane = tid & 31, warp = tid >> 5;
    const int wr = warp >> 2, wc = warp & 3;
    const int g = lane >> 2, tg = lane & 3;
    const int rowTile = blockIdx.x * 128;

    float acc[4][4][4];
    #pragma unroll
    for (int mt = 0; mt < 4; mt++)
        #pragma unroll
        for (int nt = 0; nt < 4; nt++)
            #pragma unroll
            for (int q = 0; q < 4; q++) acc[mt][nt][q] = 0.f;

    for (int k0 = 0; k0 < K; k0 += 16) {
        {
            int r = tid >> 1, c = (tid & 1) * 8;
            int gr = rowTile + r;
            float4 v0 = make_float4(0.f, 0.f, 0.f, 0.f), v1 = v0;
            if (gr < M) {
                const float* p = A + (size_t)gr * lda + k0 + c;
                v0 = *reinterpret_cast<const float4*>(p);
                v1 = *reinterpret_cast<const float4*>(p + 4);
            }
            unsigned* dst = &As[r * AS_STRIDE + c];
            dst[0] = f2tf(v0.x); dst[1] = f2tf(v0.y);
            dst[2] = f2tf(v0.z); dst[3] = f2tf(v0.w);
            dst[4] = f2tf(v1.x); dst[5] = f2tf(v1.y);
            dst[6] = f2tf(v1.z); dst[7] = f2tf(v1.w);
        }
        {
            int n = tid >> 1, c = (tid & 1) * 8;
            const float* p = W + (size_t)n * K + k0 + c;
            float4 v0 = *reinterpret_cast<const float4*>(p);
            float4 v1 = *reinterpret_cast<const float4*>(p + 4);
            Bs[(c + 0) * BS_STRIDE + n] = f2tf(v0.x);
            Bs[(c + 1) * BS_STRIDE + n] = f2tf(v0.y);
            Bs[(c + 2) * BS_STRIDE + n] = f2tf(v0.z);
            Bs[(c + 3) * BS_STRIDE + n] = f2tf(v0.w);
            Bs[(c + 4) * BS_STRIDE + n] = f2tf(v1.x);
            Bs[(c + 5) * BS_STRIDE + n] = f2tf(v1.y);
            Bs[(c + 6) * BS_STRIDE + n] = f2tf(v1.z);
            Bs[(c + 7) * BS_STRIDE + n] = f2tf(v1.w);
        }
        __syncthreads();
        #pragma unroll
        for (int ks = 0; ks < 16; ks += 8) {
            unsigned af[4][4], bf[4][2];
            #pragma unroll
            for (int mt = 0; mt < 4; mt++) {
                int r0 = (wr * 64 + mt * 16 + g) * AS_STRIDE;
                af[mt][0] = As[r0 + ks + tg];
                af[mt][1] = As[r0 + 8 * AS_STRIDE + ks + tg];
                af[mt][2] = As[r0 + ks + tg + 4];
                af[mt][3] = As[r0 + 8 * AS_STRIDE + ks + tg + 4];
            }
            #pragma unroll
            for (int nt = 0; nt < 4; nt++) {
                int n0 = wc * 32 + nt * 8 + g;
                bf[nt][0] = Bs[(ks + tg) * BS_STRIDE + n0];
                bf[nt][1] = Bs[(ks + tg + 4) * BS_STRIDE + n0];
            }
            #pragma unroll
            for (int mt = 0; mt < 4; mt++)
                #pragma unroll
                for (int nt = 0; nt < 4; nt++) mma_tf32(acc[mt][nt], af[mt], bf[nt]);
        }
        __syncthreads();
    }
    #pragma unroll
    for (int mt = 0; mt < 4; mt++) {
        int gr0 = rowTile + wr * 64 + mt * 16 + g;
        int gr1 = gr0 + 8;
        #pragma unroll
        for (int nt = 0; nt < 4; nt++) {
            int col = wc * 32 + nt * 8 + tg * 2;
            float b0 = __ldg(&bias[col]), b1 = __ldg(&bias[col + 1]);
            float v0 = acc[mt][nt][0] + b0, v1 = acc[mt][nt][1] + b1;
            float v2 = acc[mt][nt][2] + b0, v3 = acc[mt][nt][3] + b1;
            if (ACT == 1) {
                v0 = (v0 > 0.f) ? v0 : expm1f(v0);
                v1 = (v1 > 0.f) ? v1 : expm1f(v1);
                v2 = (v2 > 0.f) ? v2 : expm1f(v2);
                v3 = (v3 > 0.f) ? v3 : expm1f(v3);
            }
            if (BF16OUT) {
                __nv_bfloat16* C = (__nv_bfloat16*)Cv;
                if (gr0 < M)
                    *reinterpret_cast<__nv_bfloat162*>(&C[(size_t)gr0 * ldc + col]) =
                        __float22bfloat162_rn(make_float2(v0, v1));
                if (gr1 < M)
                    *reinterpret_cast<__nv_bfloat162*>(&C[(size_t)gr1 * ldc + col]) =
                        __float22bfloat162_rn(make_float2(v2, v3));
            } else {
                float* C = (float*)Cv;
                if (gr0 < M)
                    *reinterpret_cast<float2*>(&C[(size_t)gr0 * ldc + col]) =
                        make_float2(v0, v1);
                if (gr1 < M)
                    *reinterpret_cast<float2*>(&C[(size_t)gr1 * ldc + col]) =
                        make_float2(v2, v3);
            }
        }
    }
}

// ---------------- segment aggregations (bf16 gathers) -----------------------
// one block (64 threads) per edge: A[e] = (sum w_i X[v_i]) / (sum w_i)
__global__ void aggE_kernel() {
    int e = blockIdx.x, t = threadIdx.x;
    int beg = g_offE[e], end = g_offE[e + 1];
    __shared__ int sh_i[64];
    __shared__ float sh_c[64];
    float ax = 0.f, ay = 0.f, wsum = 0.f;
    for (int base = beg; base < end; base += 64) {
        int nn = min(64, end - base);
        __syncthreads();
        if (t < nn) {
            int v = g_sV[base + t];
            sh_i[t] = v;
            sh_c[t] = g_w[v];
        }
        __syncthreads();
        int j = 0;
        for (; j + 4 <= nn; j += 4) {
            float c0 = sh_c[j], c1 = sh_c[j + 1], c2 = sh_c[j + 2], c3 = sh_c[j + 3];
            float2 x0 = __bfloat1622float2(g_Xb[(size_t)sh_i[j] * 64 + t]);
            float2 x1 = __bfloat1622float2(g_Xb[(size_t)sh_i[j + 1] * 64 + t]);
            float2 x2 = __bfloat1622float2(g_Xb[(size_t)sh_i[j + 2] * 64 + t]);
            float2 x3 = __bfloat1622float2(g_Xb[(size_t)sh_i[j + 3] * 64 + t]);
            ax = fmaf(c0, x0.x, ax); ay = fmaf(c0, x0.y, ay);
            ax = fmaf(c1, x1.x, ax); ay = fmaf(c1, x1.y, ay);
            ax = fmaf(c2, x2.x, ax); ay = fmaf(c2, x2.y, ay);
            ax = fmaf(c3, x3.x, ax); ay = fmaf(c3, x3.y, ay);
            wsum += (c0 + c1) + (c2 + c3);
        }
        for (; j < nn; j++) {
            float c = sh_c[j];
            float2 x = __bfloat1622float2(g_Xb[(size_t)sh_i[j] * 64 + t]);
            ax = fmaf(c, x.x, ax); ay = fmaf(c, x.y, ay);
            wsum += c;
        }
    }
    float inv = (wsum > 0.f) ? 1.f / wsum : 0.f;
    *reinterpret_cast<float2*>(&g_A[(size_t)e * D + t * 2]) =
        make_float2(ax * inv, ay * inv);
}

// one block (64 threads) per node: out[n] += elu(mean_i Y[e_i])
__global__ void aggV_kernel(float* __restrict__ out) {
    int n = blockIdx.x, t = threadIdx.x;
    int beg = g_offV[n], end = g_offV[n + 1];
    __shared__ int sh_e[64];
    float ax = 0.f, ay = 0.f;
    for (int base = beg; base < end; base += 64) {
        int nn = min(64, end - base);
        __syncthreads();
        if (t < nn) sh_e[t] = g_sE[base + t];
        __syncthreads();
        int j = 0;
        for (; j + 4 <= nn; j += 4) {
            float2 y0 = __bfloat1622float2(g_Yb[(size_t)sh_e[j] * 64 + t]);
            float2 y1 = __bfloat1622float2(g_Yb[(size_t)sh_e[j + 1] * 64 + t]);
            float2 y2 = __bfloat1622float2(g_Yb[(size_t)sh_e[j + 2] * 64 + t]);
            float2 y3 = __bfloat1622float2(g_Yb[(size_t)sh_e[j + 3] * 64 + t]);
            ax += (y0.x + y1.x) + (y2.x + y3.x);
            ay += (y0.y + y1.y) + (y2.y + y3.y);
        }
        for (; j < nn; j++) {
            float2 y = __bfloat1622float2(g_Yb[(size_t)sh_e[j] * 64 + t]);
            ax += y.x; ay += y.y;
        }
    }
    int cnt = end - beg;
    float invc = 1.f / (float)(cnt > 0 ? cnt : 1);
    float xm0 = ax * invc, xm1 = ay * invc;
    xm0 = (xm0 > 0.f) ? xm0 : expm1f(xm0);
    xm1 = (xm1 > 0.f) ? xm1 : expm1f(xm1);
    float2* o2 = reinterpret_cast<float2*>(out + (size_t)n * D) + t;
    float2 o = *o2;
    o.x += xm0; o.y += xm1;
    *o2 = o;
}

// ---------------- launch -----------------------------------------------------
extern "C" void kernel_launch(void* const* d_in, const int* in_sizes, int n_in,
                              void* d_out, int out_size) {
    const float* X    = (const float*)d_in[0];
    const int*   V    = (const int*)d_in[1];
    const int*   E    = (const int*)d_in[2];
    const float* S    = (const float*)d_in[3];
    const float* Wx_w = (const float*)d_in[4];
    const float* Wx_b = (const float*)d_in[5];
    const float* Wv_w = (const float*)d_in[6];
    const float* Wv_b = (const float*)d_in[7];
    const float* a_w  = (const float*)d_in[8];
    const float* Wt_w = (const float*)d_in[9];
    const float* Wt_b = (const float*)d_in[10];
    float* out = (float*)d_out;

    float *pA = nullptr, *pZS = nullptr;
    void *pYb = nullptr;
    cudaGetSymbolAddress((void**)&pA,  g_A);
    cudaGetSymbolAddress((void**)&pZS, g_ZS);
    cudaGetSymbolAddress(&pYb, g_Yb);

    setup_kernel<<<392, 256>>>(a_w, Wv_w, Wv_b);
    mega1_kernel<<<HIST_BLOCKS + SCORE_BLOCKS + COPYS_BLOCKS, 256>>>(V, E, X, S);

    scan1_kernel<<<NBV + NBE, 1024>>>();
    scan2_kernel<<<1, 64>>>();
    scan3_kernel<<<S3V + S3E, 256>>>();

    scatter_kernel<<<(NNZV / 2 + 255) / 256, 256>>>(V, E);

    // X_init straight into the output buffer (fp32)
    gemm_tc_kernel<0, 0><<<(N_NODES + 127) / 128, 256>>>(X, D, Wx_w, Wx_b,
                                                         out, D, N_NODES, D);

    aggE_kernel<<<N_EDGES, 64>>>();

    // Z = elu(A @ Wv^T + Wv_b) into first 128 cols of g_ZS (ldc = 192)
    gemm_tc_kernel<1, 0><<<(N_EDGES + 127) / 128, 256>>>(pA, D, Wv_w, Wv_b,
                                                         pZS, DK, N_EDGES, D);

    // Y = [Z | S] @ Wt^T + Wt_b, written as bf16
    gemm_tc_kernel<0, 1><<<(N_EDGES + 127) / 128, 256>>>(pZS, DK, Wt_w, Wt_b,
                                                         pYb, D, N_EDGES, DK);

    aggV_kernel<<<N_NODES, 64>>>(out);
}